// round 2
// baseline (speedup 1.0000x reference)
#include <cuda_runtime.h>
#include <cstdint>

// BlockDecomposition RGCN layer, GB300 sm_103a
// out[n] = mask[n] * (xb[n] @ blocks[16])  +  sum_{edges (s,t,r,w), both dirs} w * (xb[s] @ blocks[r]) scattered to t
// xb: (N, 32, 4); blocks: (17, 32, 4, 4)

#define NUM_BLOCKS 32
#define BS 4
#define DIM 128           // 32 * 4
#define BLK_STRIDE 512    // floats per relation: 32*4*4

__device__ __forceinline__ void red_add_v4(float* p, float4 v) {
    asm volatile("red.global.add.v4.f32 [%0], {%1, %2, %3, %4};"
                 :: "l"(p), "f"(v.x), "f"(v.y), "f"(v.z), "f"(v.w)
                 : "memory");
}

__device__ __forceinline__ float4 block_mm(float4 xv, float4 w0, float4 w1, float4 w2, float4 w3) {
    // m[j] = sum_i x[i] * W[i][j] ; w_i = W[i][0..3]
    float4 m;
    m.x = fmaf(xv.x, w0.x, fmaf(xv.y, w1.x, fmaf(xv.z, w2.x, xv.w * w3.x)));
    m.y = fmaf(xv.x, w0.y, fmaf(xv.y, w1.y, fmaf(xv.z, w2.y, xv.w * w3.y)));
    m.z = fmaf(xv.x, w0.z, fmaf(xv.y, w1.z, fmaf(xv.z, w2.z, xv.w * w3.z)));
    m.w = fmaf(xv.x, w0.w, fmaf(xv.y, w1.w, fmaf(xv.z, w2.w, xv.w * w3.w)));
    return m;
}

// One warp per node: self-loop transform + mask, initializes out.
__global__ void __launch_bounds__(256) self_loop_kernel(
    const float* __restrict__ x,
    const int* __restrict__ keep_mask,   // bool materialized as int32
    const float* __restrict__ blocks,
    float* __restrict__ out,
    int n_nodes)
{
    int warp = (blockIdx.x * blockDim.x + threadIdx.x) >> 5;
    int lane = threadIdx.x & 31;
    if (warp >= n_nodes) return;

    const float4 xv = *reinterpret_cast<const float4*>(x + (size_t)warp * DIM + lane * BS);
    const float4* wp = reinterpret_cast<const float4*>(blocks + 16 * BLK_STRIDE + lane * 16);
    float4 w0 = wp[0], w1 = wp[1], w2 = wp[2], w3 = wp[3];

    float4 m = block_mm(xv, w0, w1, w2, w3);
    if (keep_mask[warp] == 0) { m.x = 0.f; m.y = 0.f; m.z = 0.f; m.w = 0.f; }
    *reinterpret_cast<float4*>(out + (size_t)warp * DIM + lane * BS) = m;
}

// One warp per (undirected) edge: processes both directions.
// Lane b owns diagonal block b (4 inputs -> 4 outputs).
__global__ void __launch_bounds__(256) edge_kernel(
    const float* __restrict__ x,
    const int* __restrict__ src,
    const int* __restrict__ tgt,
    const int* __restrict__ etype,
    const float* __restrict__ eweight,
    const float* __restrict__ blocks,
    float* __restrict__ out,
    int n_edges)
{
    int warp = (blockIdx.x * blockDim.x + threadIdx.x) >> 5;
    int lane = threadIdx.x & 31;
    if (warp >= n_edges) return;

    int s = src[warp];
    int t = tgt[warp];
    int r = etype[warp];
    float w = eweight[warp];

    // relation block for lane's diagonal block: 16 floats, L1-resident (32KB table)
    const float4* wp = reinterpret_cast<const float4*>(blocks + (size_t)r * BLK_STRIDE + lane * 16);
    float4 w0 = wp[0], w1 = wp[1], w2 = wp[2], w3 = wp[3];

    // direction s -> t
    float4 xs = *reinterpret_cast<const float4*>(x + (size_t)s * DIM + lane * BS);
    float4 m1 = block_mm(xs, w0, w1, w2, w3);
    m1.x *= w; m1.y *= w; m1.z *= w; m1.w *= w;

    // direction t -> s (same relation, same weight)
    float4 xt = *reinterpret_cast<const float4*>(x + (size_t)t * DIM + lane * BS);
    float4 m2 = block_mm(xt, w0, w1, w2, w3);
    m2.x *= w; m2.y *= w; m2.z *= w; m2.w *= w;

    red_add_v4(out + (size_t)t * DIM + lane * BS, m1);
    red_add_v4(out + (size_t)s * DIM + lane * BS, m2);
}

extern "C" void kernel_launch(void* const* d_in, const int* in_sizes, int n_in,
                              void* d_out, int out_size)
{
    const float* x      = (const float*)d_in[0];
    const int*   mask   = (const int*)d_in[1];
    const int*   src    = (const int*)d_in[2];
    const int*   tgt    = (const int*)d_in[3];
    const int*   etype  = (const int*)d_in[4];
    const float* ew     = (const float*)d_in[5];
    const float* blocks = (const float*)d_in[6];
    float*       out    = (float*)d_out;

    int n_nodes = in_sizes[0] / DIM;
    int n_edges = in_sizes[2];

    // Kernel 1: initialize out with masked self-loop messages (one warp/node)
    {
        int total_threads = n_nodes * 32;
        int threads = 256;
        int grid = (total_threads + threads - 1) / threads;
        self_loop_kernel<<<grid, threads>>>(x, mask, blocks, out, n_nodes);
    }

    // Kernel 2: edge messages, both directions, vectorized reductions (one warp/edge)
    {
        int total_threads = n_edges * 32;
        int threads = 256;
        int grid = (total_threads + threads - 1) / threads;
        edge_kernel<<<grid, threads>>>(x, src, tgt, etype, ew, blocks, out, n_edges);
    }
}

// round 3
// speedup vs baseline: 1.3555x; 1.3555x over previous
#include <cuda_runtime.h>
#include <cstdint>

// BlockDecomposition RGCN layer, GB300 sm_103a
// out[n] = mask[n] * (xb[n] @ blocks[16]) + sum_{edges (s,t,r,w), both dirs} w * (xb[s] @ blocks[r]) -> t
// xb: (N, 32, 4); blocks: (17, 32, 4, 4)

#define NUM_BLOCKS 32
#define BS 4
#define DIM 128           // 32 * 4
#define BLK_STRIDE 512    // floats per relation: 32*4*4
#define NUM_REL_TOT 17

// Transposed weight scratch: W'[r][i][b][j] = blocks[r][b][i][j]
// so a warp (lane=b) reads each i-row as one contiguous 512B LDG.128 span.
__device__ float g_wt[NUM_REL_TOT * BLK_STRIDE];

__device__ __forceinline__ void red_add_v4(float* p, float4 v) {
    asm volatile("red.global.add.v4.f32 [%0], {%1, %2, %3, %4};"
                 :: "l"(p), "f"(v.x), "f"(v.y), "f"(v.z), "f"(v.w)
                 : "memory");
}

__device__ __forceinline__ float4 block_mm(float4 xv, float4 w0, float4 w1, float4 w2, float4 w3) {
    // m[j] = sum_i x[i] * W[i][j] ; w_i = W[i][0..3]
    float4 m;
    m.x = fmaf(xv.x, w0.x, fmaf(xv.y, w1.x, fmaf(xv.z, w2.x, xv.w * w3.x)));
    m.y = fmaf(xv.x, w0.y, fmaf(xv.y, w1.y, fmaf(xv.z, w2.y, xv.w * w3.y)));
    m.z = fmaf(xv.x, w0.z, fmaf(xv.y, w1.z, fmaf(xv.z, w2.z, xv.w * w3.z)));
    m.w = fmaf(xv.x, w0.w, fmaf(xv.y, w1.w, fmaf(xv.z, w2.w, xv.w * w3.w)));
    return m;
}

// One warp per node: self-loop transform + mask, initializes out.
// Blocks 0..16 additionally transpose one relation's weights into g_wt.
__global__ void __launch_bounds__(256) self_loop_kernel(
    const float* __restrict__ x,
    const int* __restrict__ keep_mask,   // bool materialized as int32
    const float* __restrict__ blocks,
    float* __restrict__ out,
    int n_nodes)
{
    // weight transpose: block r handles relation r (512 floats, 2 per thread)
    if (blockIdx.x < NUM_REL_TOT) {
        int r = blockIdx.x;
        #pragma unroll
        for (int k = 0; k < 2; k++) {
            int idx = threadIdx.x + k * 256;        // 0..511
            int b = idx >> 4;                        // block index
            int i = (idx >> 2) & 3;                  // input row
            int j = idx & 3;                         // output col
            g_wt[r * BLK_STRIDE + i * 128 + b * 4 + j] = blocks[r * BLK_STRIDE + idx];
        }
    }

    int warp = (blockIdx.x * blockDim.x + threadIdx.x) >> 5;
    int lane = threadIdx.x & 31;
    if (warp >= n_nodes) return;

    const float4 xv = *reinterpret_cast<const float4*>(x + (size_t)warp * DIM + lane * BS);
    const float4* wp = reinterpret_cast<const float4*>(blocks + 16 * BLK_STRIDE + lane * 16);
    float4 w0 = wp[0], w1 = wp[1], w2 = wp[2], w3 = wp[3];

    float4 m = block_mm(xv, w0, w1, w2, w3);
    if (keep_mask[warp] == 0) { m.x = 0.f; m.y = 0.f; m.z = 0.f; m.w = 0.f; }
    *reinterpret_cast<float4*>(out + (size_t)warp * DIM + lane * BS) = m;
}

// One warp per (undirected) edge: processes both directions.
// Lane b owns diagonal block b. Weights read from transposed g_wt (coalesced).
__global__ void __launch_bounds__(256) edge_kernel(
    const float* __restrict__ x,
    const int* __restrict__ src,
    const int* __restrict__ tgt,
    const int* __restrict__ etype,
    const float* __restrict__ eweight,
    float* __restrict__ out,
    int n_edges)
{
    int warp = (blockIdx.x * blockDim.x + threadIdx.x) >> 5;
    int lane = threadIdx.x & 31;
    if (warp >= n_edges) return;

    int s = src[warp];
    int t = tgt[warp];
    int r = etype[warp];
    float w = eweight[warp];

    // coalesced weight fetch: each i-row is one contiguous 512B span per warp
    const float* wbase = g_wt + (size_t)r * BLK_STRIDE + lane * 4;
    float4 w0 = *reinterpret_cast<const float4*>(wbase);
    float4 w1 = *reinterpret_cast<const float4*>(wbase + 128);
    float4 w2 = *reinterpret_cast<const float4*>(wbase + 256);
    float4 w3 = *reinterpret_cast<const float4*>(wbase + 384);

    // direction s -> t
    float4 xs = *reinterpret_cast<const float4*>(x + (size_t)s * DIM + lane * BS);
    float4 m1 = block_mm(xs, w0, w1, w2, w3);
    m1.x *= w; m1.y *= w; m1.z *= w; m1.w *= w;

    // direction t -> s (same relation, same weight)
    float4 xt = *reinterpret_cast<const float4*>(x + (size_t)t * DIM + lane * BS);
    float4 m2 = block_mm(xt, w0, w1, w2, w3);
    m2.x *= w; m2.y *= w; m2.z *= w; m2.w *= w;

    red_add_v4(out + (size_t)t * DIM + lane * BS, m1);
    red_add_v4(out + (size_t)s * DIM + lane * BS, m2);
}

extern "C" void kernel_launch(void* const* d_in, const int* in_sizes, int n_in,
                              void* d_out, int out_size)
{
    const float* x      = (const float*)d_in[0];
    const int*   mask   = (const int*)d_in[1];
    const int*   src    = (const int*)d_in[2];
    const int*   tgt    = (const int*)d_in[3];
    const int*   etype  = (const int*)d_in[4];
    const float* ew     = (const float*)d_in[5];
    const float* blocks = (const float*)d_in[6];
    float*       out    = (float*)d_out;

    int n_nodes = in_sizes[0] / DIM;
    int n_edges = in_sizes[2];

    // Kernel 1: init out with masked self-loop messages + transpose weights into g_wt
    {
        int total_threads = n_nodes * 32;
        int threads = 256;
        int grid = (total_threads + threads - 1) / threads;
        self_loop_kernel<<<grid, threads>>>(x, mask, blocks, out, n_nodes);
    }

    // Kernel 2: edge messages, both directions, vectorized reductions (one warp/edge)
    {
        int total_threads = n_edges * 32;
        int threads = 256;
        int grid = (total_threads + threads - 1) / threads;
        edge_kernel<<<grid, threads>>>(x, src, tgt, etype, ew, out, n_edges);
    }
}